// round 2
// baseline (speedup 1.0000x reference)
#include <cuda_runtime.h>
#include <math.h>

// Problem constants (fixed by dataset)
#define NMAX 50000
#define EMAX 800000
#define D1   128     // heads*hid = 4*32
#define HEADS 4
#define HID  32
#define OUTF 40
#define LN_EPS 1e-5f

// ---------------- scratch (device globals; no allocation allowed) ------------
__device__ float g_xl1[NMAX * D1];
__device__ float g_xr1[NMAX * D1];
__device__ float g_h1 [NMAX * D1];
__device__ float g_xl2[NMAX * OUTF];
__device__ float g_xr2[NMAX * OUTF];
__device__ float g_e1 [EMAX * HEADS];  // CSR order
__device__ float g_e2 [EMAX];          // CSR order
__device__ int   g_src[EMAX];
__device__ int   g_tgt[EMAX];
__device__ int   g_csrc[EMAX];         // src per CSR slot
__device__ int   g_ctgt[EMAX];         // tgt per CSR slot
__device__ int   g_cnt[NMAX];
__device__ int   g_rowptr[NMAX + 1];
__device__ int   g_cursor[NMAX];
__device__ int   g_is64;

__device__ __forceinline__ float lrelu(float x) { return x > 0.f ? x : 0.2f * x; }

// ---------------- edge index dtype detection + normalization ----------------
__global__ void detect_kernel(const int* raw) {
    if (threadIdx.x == 0) {
        int ok = 1;
        #pragma unroll
        for (int i = 0; i < 8; i++)
            if (raw[2 * i + 1] != 0) ok = 0;   // int64 < 2^31 -> hi words zero
        g_is64 = ok;
    }
}

__global__ void convert_kernel(const void* raw, int E) {
    int i = blockIdx.x * blockDim.x + threadIdx.x;
    if (i >= E) return;
    if (g_is64) {
        const long long* p = (const long long*)raw;
        g_src[i] = (int)p[i];
        g_tgt[i] = (int)p[E + i];
    } else {
        const int* p = (const int*)raw;
        g_src[i] = p[i];
        g_tgt[i] = p[E + i];
    }
}

// ---------------- CSR build: histogram -> scan -> scatter --------------------
__global__ void zero_cnt_kernel(int n) {
    int i = blockIdx.x * blockDim.x + threadIdx.x;
    if (i < n) g_cnt[i] = 0;
}

__global__ void hist_kernel(int E) {
    int i = blockIdx.x * blockDim.x + threadIdx.x;
    if (i < E) atomicAdd(&g_cnt[g_tgt[i]], 1);
}

__global__ void scan_kernel(int n) {
    __shared__ int sh[1024];
    int tid = threadIdx.x;
    int carry = 0;
    for (int base = 0; base < n; base += 1024) {
        int v = (base + tid < n) ? g_cnt[base + tid] : 0;
        sh[tid] = v;
        __syncthreads();
        int x = v;
        for (int off = 1; off < 1024; off <<= 1) {
            int t = (tid >= off) ? sh[tid - off] : 0;
            __syncthreads();
            x += t;
            sh[tid] = x;
            __syncthreads();
        }
        int excl = x - v;
        if (base + tid < n) {
            g_rowptr[base + tid] = carry + excl;
            g_cursor[base + tid] = carry + excl;
        }
        int total = sh[1023];
        __syncthreads();
        carry += total;
    }
    if (tid == 0) g_rowptr[n] = carry;
}

__global__ void scatter_kernel(int E) {
    int i = blockIdx.x * blockDim.x + threadIdx.x;
    if (i >= E) return;
    int t = g_tgt[i];
    int pos = atomicAdd(&g_cursor[t], 1);
    g_csrc[pos] = g_src[i];
    g_ctgt[pos] = t;
}

// ---------------- tiled fp32 GEMM body: C = A[n,128] @ W[128,oc] + b ---------
__device__ __forceinline__ void gemm_body(const float* __restrict__ A,
                                          const float* __restrict__ W,
                                          const float* __restrict__ bias,
                                          float* __restrict__ C,
                                          int n, int oc, int bRow, int bCol) {
    __shared__ float As[64][65];
    __shared__ float Bs[64][64];
    int tid = threadIdx.x;       // 256 threads
    int tx = tid & 15, ty = tid >> 4;
    float acc[4][4];
    #pragma unroll
    for (int i = 0; i < 4; i++)
        #pragma unroll
        for (int j = 0; j < 4; j++) acc[i][j] = 0.f;

    for (int kt = 0; kt < 128; kt += 64) {
        #pragma unroll
        for (int i = 0; i < 16; i++) {
            int idx = tid + 256 * i;
            int r = idx >> 6, c = idx & 63;
            int gr = bRow + r;
            As[r][c] = (gr < n) ? A[gr * 128 + kt + c] : 0.f;
        }
        #pragma unroll
        for (int i = 0; i < 16; i++) {
            int idx = tid + 256 * i;
            int r = idx >> 6, c = idx & 63;
            int gc = bCol + c;
            Bs[r][c] = (gc < oc) ? W[(kt + r) * oc + gc] : 0.f;
        }
        __syncthreads();
        #pragma unroll
        for (int k = 0; k < 64; k++) {
            float a[4], b[4];
            #pragma unroll
            for (int i = 0; i < 4; i++) a[i] = As[ty + 16 * i][k];
            #pragma unroll
            for (int j = 0; j < 4; j++) b[j] = Bs[k][tx + 16 * j];
            #pragma unroll
            for (int i = 0; i < 4; i++)
                #pragma unroll
                for (int j = 0; j < 4; j++) acc[i][j] += a[i] * b[j];
        }
        __syncthreads();
    }
    #pragma unroll
    for (int i = 0; i < 4; i++) {
        int gr = bRow + ty + 16 * i;
        if (gr >= n) continue;
        #pragma unroll
        for (int j = 0; j < 4; j++) {
            int gc = bCol + tx + 16 * j;
            if (gc < oc) C[gr * oc + gc] = acc[i][j] + bias[gc];
        }
    }
}

// layer-1: both transforms in one launch. grid.y in [0,4):
//   y&1 -> column block; y>>1 -> 0: (Wl1 -> g_xl1), 1: (Wr1 -> g_xr1)
__global__ void gemm1_kernel(const float* __restrict__ x,
                             const float* __restrict__ Wl,
                             const float* __restrict__ bl,
                             const float* __restrict__ Wr,
                             const float* __restrict__ br, int n) {
    int bRow = blockIdx.x * 64;
    int cb = (blockIdx.y & 1) * 64;
    if (blockIdx.y < 2) gemm_body(x, Wl, bl, g_xl1, n, 128, bRow, cb);
    else                gemm_body(x, Wr, br, g_xr1, n, 128, bRow, cb);
}

// layer-2: grid.y in [0,2): 0 -> (Wl2 -> g_xl2), 1 -> (Wr2 -> g_xr2)
__global__ void gemm2_kernel(const float* __restrict__ Wl,
                             const float* __restrict__ bl,
                             const float* __restrict__ Wr,
                             const float* __restrict__ br, int n) {
    int bRow = blockIdx.x * 64;
    if (blockIdx.y == 0) gemm_body(g_h1, Wl, bl, g_xl2, n, OUTF, bRow, 0);
    else                 gemm_body(g_h1, Wr, br, g_xr2, n, OUTF, bRow, 0);
}

// ---------------- layer-1 edge scores in CSR order: e1[p,4] ------------------
__global__ void score1_kernel(const float* __restrict__ att1, int E) {
    int p = (blockIdx.x * blockDim.x + threadIdx.x) >> 5;
    int lane = threadIdx.x & 31;
    if (p >= E) return;
    int s = g_csrc[p], t = g_ctgt[p];
    float4 a = *(const float4*)(g_xl1 + (size_t)s * D1 + lane * 4);
    float4 b = *(const float4*)(g_xr1 + (size_t)t * D1 + lane * 4);
    float4 w = *(const float4*)(att1 + lane * 4);
    float sum = lrelu(a.x + b.x) * w.x + lrelu(a.y + b.y) * w.y +
                lrelu(a.z + b.z) * w.z + lrelu(a.w + b.w) * w.w;
    sum += __shfl_down_sync(0xffffffffu, sum, 4);
    sum += __shfl_down_sync(0xffffffffu, sum, 2);
    sum += __shfl_down_sync(0xffffffffu, sum, 1);
    if ((lane & 7) == 0) g_e1[(size_t)p * 4 + (lane >> 3)] = sum;
}

// ---------------- layer-1 softmax+aggregate + bias + LN + ELU ----------------
__global__ void agg1_kernel(const float* __restrict__ b1,
                            const float* __restrict__ g1,
                            const float* __restrict__ be1, int n) {
    int node = (blockIdx.x * blockDim.x + threadIdx.x) >> 5;
    int lane = threadIdx.x & 31;
    if (node >= n) return;
    int beg = g_rowptr[node], end = g_rowptr[node + 1];

    // pass 1: per-head max (lane-strided, contiguous e1 reads)
    float m0 = -1e30f, m1 = -1e30f, m2 = -1e30f, m3 = -1e30f;
    for (int p = beg + lane; p < end; p += 32) {
        float4 ev = *(const float4*)(g_e1 + (size_t)p * 4);
        m0 = fmaxf(m0, ev.x); m1 = fmaxf(m1, ev.y);
        m2 = fmaxf(m2, ev.z); m3 = fmaxf(m3, ev.w);
    }
    #pragma unroll
    for (int off = 16; off > 0; off >>= 1) {
        m0 = fmaxf(m0, __shfl_xor_sync(0xffffffffu, m0, off));
        m1 = fmaxf(m1, __shfl_xor_sync(0xffffffffu, m1, off));
        m2 = fmaxf(m2, __shfl_xor_sync(0xffffffffu, m2, off));
        m3 = fmaxf(m3, __shfl_xor_sync(0xffffffffu, m3, off));
    }
    // pass 2: exp + sum; store exp back (avoids exp recompute in pass 3)
    float s0 = 0.f, s1 = 0.f, s2 = 0.f, s3 = 0.f;
    for (int p = beg + lane; p < end; p += 32) {
        float4 ev = *(const float4*)(g_e1 + (size_t)p * 4);
        ev.x = __expf(ev.x - m0); ev.y = __expf(ev.y - m1);
        ev.z = __expf(ev.z - m2); ev.w = __expf(ev.w - m3);
        s0 += ev.x; s1 += ev.y; s2 += ev.z; s3 += ev.w;
        *(float4*)(g_e1 + (size_t)p * 4) = ev;
    }
    #pragma unroll
    for (int off = 16; off > 0; off >>= 1) {
        s0 += __shfl_xor_sync(0xffffffffu, s0, off);
        s1 += __shfl_xor_sync(0xffffffffu, s1, off);
        s2 += __shfl_xor_sync(0xffffffffu, s2, off);
        s3 += __shfl_xor_sync(0xffffffffu, s3, off);
    }
    int h = lane >> 3;
    float sh = (h == 0) ? s0 : (h == 1) ? s1 : (h == 2) ? s2 : s3;
    float inv = 1.f / (sh + 1e-16f);

    // pass 3: weighted aggregation, whole warp per edge
    float4 acc = make_float4(0.f, 0.f, 0.f, 0.f);
    for (int p = beg; p < end; p++) {
        int s = g_csrc[p];
        float alpha = g_e1[(size_t)p * 4 + h] * inv;
        float4 v = *(const float4*)(g_xl1 + (size_t)s * D1 + lane * 4);
        acc.x += alpha * v.x; acc.y += alpha * v.y;
        acc.z += alpha * v.z; acc.w += alpha * v.w;
    }
    float4 bb = *(const float4*)(b1 + lane * 4);
    acc.x += bb.x; acc.y += bb.y; acc.z += bb.z; acc.w += bb.w;

    // LayerNorm over 128 features (warp-wide)
    float psum = acc.x + acc.y + acc.z + acc.w;
    float psq  = acc.x * acc.x + acc.y * acc.y + acc.z * acc.z + acc.w * acc.w;
    #pragma unroll
    for (int off = 16; off > 0; off >>= 1) {
        psum += __shfl_xor_sync(0xffffffffu, psum, off);
        psq  += __shfl_xor_sync(0xffffffffu, psq,  off);
    }
    float mean = psum * (1.f / 128.f);
    float var  = psq * (1.f / 128.f) - mean * mean;
    float rstd = rsqrtf(var + LN_EPS);
    float4 gg = *(const float4*)(g1  + lane * 4);
    float4 ee = *(const float4*)(be1 + lane * 4);
    float y0 = (acc.x - mean) * rstd * gg.x + ee.x;
    float y1 = (acc.y - mean) * rstd * gg.y + ee.y;
    float y2 = (acc.z - mean) * rstd * gg.z + ee.z;
    float y3 = (acc.w - mean) * rstd * gg.w + ee.w;
    y0 = y0 > 0.f ? y0 : expm1f(y0);
    y1 = y1 > 0.f ? y1 : expm1f(y1);
    y2 = y2 > 0.f ? y2 : expm1f(y2);
    y3 = y3 > 0.f ? y3 : expm1f(y3);
    *(float4*)(g_h1 + (size_t)node * D1 + lane * 4) = make_float4(y0, y1, y2, y3);
}

// ---------------- layer-2 edge scores in CSR order: e2[p] --------------------
__global__ void score2_kernel(const float* __restrict__ att2, int E) {
    int gtid = blockIdx.x * blockDim.x + threadIdx.x;
    int warp = gtid >> 5;
    int lane = threadIdx.x & 31;
    int p = warp * 4 + (lane >> 3);   // 8 lanes per edge, 4 edges per warp
    int j = lane & 7;
    float sum = 0.f;
    if (p < E) {
        int s = g_csrc[p], t = g_ctgt[p];
        const float* xl = g_xl2 + (size_t)s * OUTF;
        const float* xr = g_xr2 + (size_t)t * OUTF;
        #pragma unroll
        for (int k = 0; k < 5; k++) {
            int c = j + 8 * k;
            sum += lrelu(xl[c] + xr[c]) * att2[c];
        }
    }
    sum += __shfl_down_sync(0xffffffffu, sum, 4);
    sum += __shfl_down_sync(0xffffffffu, sum, 2);
    sum += __shfl_down_sync(0xffffffffu, sum, 1);
    if (j == 0 && p < E) g_e2[p] = sum;
}

// ---------------- layer-2 softmax+aggregate -> output ------------------------
__global__ void agg2_kernel(const float* __restrict__ b2, float* __restrict__ out, int n) {
    int node = (blockIdx.x * blockDim.x + threadIdx.x) >> 5;
    int lane = threadIdx.x & 31;
    if (node >= n) return;
    int beg = g_rowptr[node], end = g_rowptr[node + 1];

    float m = -1e30f;
    for (int p = beg + lane; p < end; p += 32) m = fmaxf(m, g_e2[p]);
    #pragma unroll
    for (int off = 16; off > 0; off >>= 1)
        m = fmaxf(m, __shfl_xor_sync(0xffffffffu, m, off));
    float s = 0.f;
    for (int p = beg + lane; p < end; p += 32) {
        float v = __expf(g_e2[p] - m);
        g_e2[p] = v;
        s += v;
    }
    #pragma unroll
    for (int off = 16; off > 0; off >>= 1)
        s += __shfl_xor_sync(0xffffffffu, s, off);
    float inv = 1.f / (s + 1e-16f);

    float acc0 = 0.f, acc1 = 0.f;
    for (int p = beg; p < end; p++) {
        int sr = g_csrc[p];
        float alpha = g_e2[p] * inv;
        const float* xl = g_xl2 + (size_t)sr * OUTF;
        acc0 += alpha * xl[lane];
        if (lane < 8) acc1 += alpha * xl[lane + 32];
    }
    out[(size_t)node * OUTF + lane] = acc0 + b2[lane];
    if (lane < 8) out[(size_t)node * OUTF + 32 + lane] = acc1 + b2[32 + lane];
}

// ---------------- launch -----------------------------------------------------
extern "C" void kernel_launch(void* const* d_in, const int* in_sizes, int n_in,
                              void* d_out, int out_size) {
    const float* x    = (const float*)d_in[0];
    const void*  eidx = d_in[1];
    const float* Wl1  = (const float*)d_in[2];
    const float* bl1  = (const float*)d_in[3];
    const float* Wr1  = (const float*)d_in[4];
    const float* br1  = (const float*)d_in[5];
    const float* att1 = (const float*)d_in[6];
    const float* b1   = (const float*)d_in[7];
    const float* g1   = (const float*)d_in[8];
    const float* be1  = (const float*)d_in[9];
    const float* Wl2  = (const float*)d_in[10];
    const float* bl2  = (const float*)d_in[11];
    const float* Wr2  = (const float*)d_in[12];
    const float* br2  = (const float*)d_in[13];
    const float* att2 = (const float*)d_in[14];
    const float* b2   = (const float*)d_in[15];
    float* out = (float*)d_out;

    int n = in_sizes[0] / 128;
    int E = in_sizes[1] / 2;

    // normalize edge indices (detect int32 vs int64 on device)
    detect_kernel<<<1, 32>>>((const int*)eidx);
    convert_kernel<<<(E + 255) / 256, 256>>>(eidx, E);

    // CSR by target
    zero_cnt_kernel<<<(n + 255) / 256, 256>>>(n);
    hist_kernel<<<(E + 255) / 256, 256>>>(E);
    scan_kernel<<<1, 1024>>>(n);
    scatter_kernel<<<(E + 255) / 256, 256>>>(E);

    // layer 1 GEMMs (xl1, xr1 in one launch)
    {
        dim3 grid((n + 63) / 64, 4);
        gemm1_kernel<<<grid, 256>>>(x, Wl1, bl1, Wr1, br1, n);
    }
    // layer 1 edge scores (1 warp per CSR slot)
    score1_kernel<<<(E + 7) / 8, 256>>>(att1, E);
    // layer 1 softmax + aggregate + bias + LN + ELU (1 warp per node)
    agg1_kernel<<<(n + 7) / 8, 256>>>(b1, g1, be1, n);

    // layer 2 GEMMs (xl2, xr2 in one launch)
    {
        dim3 grid((n + 63) / 64, 2);
        gemm2_kernel<<<grid, 256>>>(Wl2, bl2, Wr2, br2, n);
    }
    // layer 2 edge scores (4 edges per warp)
    score2_kernel<<<(E + 31) / 32, 256>>>(att2, E);
    // layer 2 softmax + aggregate -> output
    agg2_kernel<<<(n + 7) / 8, 256>>>(b2, out, n);
}

// round 5
// speedup vs baseline: 1.3757x; 1.3757x over previous
#include <cuda_runtime.h>
#include <math.h>

// Problem constants (fixed by dataset)
#define NMAX 50000
#define EMAX 800000
#define D1   128     // heads*hid = 4*32
#define HEADS 4
#define HID  32
#define OUTF 40
#define LN_EPS 1e-5f

// ---------------- scratch (device globals; no allocation allowed) ------------
__device__ float g_xl1[NMAX * D1];
__device__ float g_xr1[NMAX * D1];
__device__ float g_h1 [NMAX * D1];
__device__ float g_xl2[NMAX * OUTF];
__device__ float g_xr2[NMAX * OUTF];
__device__ float g_e1 [EMAX * HEADS];  // CSR order
__device__ float g_e2 [EMAX];          // CSR order
__device__ int   g_src[EMAX];
__device__ int   g_tgt[EMAX];
__device__ int   g_csrc[EMAX];         // src per CSR slot
__device__ int   g_cnt[NMAX];
__device__ int   g_rowptr[NMAX + 1];
__device__ int   g_cursor[NMAX];
__device__ int   g_bsum[256];
__device__ int   g_boff[256];
__device__ int   g_is64;

__device__ __forceinline__ float lrelu(float x) { return x > 0.f ? x : 0.2f * x; }

// ---------------- edge index dtype detection ---------------------------------
__global__ void detect_kernel(const int* raw) {
    if (threadIdx.x == 0) {
        int ok = 1;
        #pragma unroll
        for (int i = 0; i < 8; i++)
            if (raw[2 * i + 1] != 0) ok = 0;   // int64 < 2^31 -> hi words zero
        g_is64 = ok;
    }
}

__global__ void zero_cnt_kernel(int n) {
    int i = blockIdx.x * blockDim.x + threadIdx.x;
    if (i < n) g_cnt[i] = 0;
}

// convert + histogram in one pass
__global__ void convert_hist_kernel(const void* raw, int E) {
    int i = blockIdx.x * blockDim.x + threadIdx.x;
    if (i >= E) return;
    int s, t;
    if (g_is64) {
        const long long* p = (const long long*)raw;
        s = (int)p[i]; t = (int)p[E + i];
    } else {
        const int* p = (const int*)raw;
        s = p[i]; t = p[E + i];
    }
    g_src[i] = s;
    g_tgt[i] = t;
    atomicAdd(&g_cnt[t], 1);
}

// ---------------- parallel exclusive scan (3 kernels) ------------------------
__device__ __forceinline__ int excl_scan_block(int v, int* wsum, int& total) {
    const unsigned full = 0xffffffffu;
    int lane = threadIdx.x & 31, w = threadIdx.x >> 5;
    int x = v;
    #pragma unroll
    for (int off = 1; off < 32; off <<= 1) {
        int t = __shfl_up_sync(full, x, off);
        if (lane >= off) x += t;
    }
    if (lane == 31) wsum[w] = x;
    __syncthreads();
    if (w == 0) {
        int s = (lane < 8) ? wsum[lane] : 0;
        #pragma unroll
        for (int off = 1; off < 8; off <<= 1) {
            int t = __shfl_up_sync(full, s, off);
            if (lane >= off) s += t;
        }
        if (lane < 8) wsum[lane] = s;
    }
    __syncthreads();
    int base = (w > 0) ? wsum[w - 1] : 0;
    total = wsum[7];
    return base + x - v;
}

__global__ void scan_a_kernel(int n) {
    __shared__ int wsum[8];
    int i = blockIdx.x * 256 + threadIdx.x;
    int v = (i < n) ? g_cnt[i] : 0;
    int total;
    int ex = excl_scan_block(v, wsum, total);
    if (i < n) g_rowptr[i] = ex;
    if (threadIdx.x == 0) g_bsum[blockIdx.x] = total;
}

__global__ void scan_b_kernel(int nb) {
    __shared__ int wsum[8];
    int b = threadIdx.x;
    int v = (b < nb) ? g_bsum[b] : 0;
    int total;
    int ex = excl_scan_block(v, wsum, total);
    if (b < nb) g_boff[b] = ex;
}

__global__ void scan_c_kernel(int n, int E) {
    int i = blockIdx.x * 256 + threadIdx.x;
    if (i < n) {
        int rp = g_rowptr[i] + g_boff[blockIdx.x];
        g_rowptr[i] = rp;
        g_cursor[i] = rp;
    }
    if (i == 0) g_rowptr[n] = E;
}

__global__ void scatter_kernel(int E) {
    int i = blockIdx.x * blockDim.x + threadIdx.x;
    if (i >= E) return;
    int t = g_tgt[i];
    int pos = atomicAdd(&g_cursor[t], 1);
    g_csrc[pos] = g_src[i];
}

// ---------------- layer-1 GEMM: 128x128 tile, 8x8/thread, FFMA-bound ---------
// C = A[n,128] @ W[128,128] + bias ; grid.y selects (Wl->xl1) / (Wr->xr1)
__global__ __launch_bounds__(256, 2) void gemm1_kernel(
        const float* __restrict__ x,
        const float* __restrict__ Wl, const float* __restrict__ bl,
        const float* __restrict__ Wr, const float* __restrict__ br, int n) {
    __shared__ float Ast[32][132];   // transposed A tile: Ast[k][row]
    __shared__ float Bs[32][128];
    const float* W    = (blockIdx.y == 0) ? Wl : Wr;
    const float* bias = (blockIdx.y == 0) ? bl : br;
    float* C          = (blockIdx.y == 0) ? g_xl1 : g_xr1;
    int bRow = blockIdx.x * 128;
    int tid = threadIdx.x;
    int tx = tid & 15, ty = tid >> 4;
    float acc[8][8];
    #pragma unroll
    for (int i = 0; i < 8; i++)
        #pragma unroll
        for (int j = 0; j < 8; j++) acc[i][j] = 0.f;

    for (int kt = 0; kt < 128; kt += 32) {
        #pragma unroll
        for (int it = 0; it < 4; it++) {
            int slot = tid + it * 256;       // 0..1023
            int r = slot >> 3;               // 0..127
            int k4 = (slot & 7) * 4;         // 0..28
            int gr = bRow + r;
            float4 av = (gr < n) ? *(const float4*)(x + (size_t)gr * 128 + kt + k4)
                                 : make_float4(0.f, 0.f, 0.f, 0.f);
            Ast[k4 + 0][r] = av.x; Ast[k4 + 1][r] = av.y;
            Ast[k4 + 2][r] = av.z; Ast[k4 + 3][r] = av.w;
        }
        #pragma unroll
        for (int it = 0; it < 4; it++) {
            int slot = tid + it * 256;
            int k = slot >> 5;               // 0..31
            int c4 = (slot & 31) * 4;        // 0..124
            *(float4*)(&Bs[k][c4]) = *(const float4*)(W + (size_t)(kt + k) * 128 + c4);
        }
        __syncthreads();
        #pragma unroll
        for (int k = 0; k < 32; k++) {
            float4 a0 = *(const float4*)(&Ast[k][ty * 8]);
            float4 a1 = *(const float4*)(&Ast[k][ty * 8 + 4]);
            float4 b0 = *(const float4*)(&Bs[k][tx * 8]);
            float4 b1 = *(const float4*)(&Bs[k][tx * 8 + 4]);
            float a[8] = {a0.x, a0.y, a0.z, a0.w, a1.x, a1.y, a1.z, a1.w};
            float b[8] = {b0.x, b0.y, b0.z, b0.w, b1.x, b1.y, b1.z, b1.w};
            #pragma unroll
            for (int i = 0; i < 8; i++)
                #pragma unroll
                for (int j = 0; j < 8; j++) acc[i][j] += a[i] * b[j];
        }
        __syncthreads();
    }
    #pragma unroll
    for (int i = 0; i < 8; i++) {
        int gr = bRow + ty * 8 + i;
        if (gr >= n) continue;
        float4 o0, o1;
        o0.x = acc[i][0] + bias[tx * 8 + 0]; o0.y = acc[i][1] + bias[tx * 8 + 1];
        o0.z = acc[i][2] + bias[tx * 8 + 2]; o0.w = acc[i][3] + bias[tx * 8 + 3];
        o1.x = acc[i][4] + bias[tx * 8 + 4]; o1.y = acc[i][5] + bias[tx * 8 + 5];
        o1.z = acc[i][6] + bias[tx * 8 + 6]; o1.w = acc[i][7] + bias[tx * 8 + 7];
        *(float4*)(C + (size_t)gr * 128 + tx * 8)     = o0;
        *(float4*)(C + (size_t)gr * 128 + tx * 8 + 4) = o1;
    }
}

// ---------------- layer-2 GEMM (64x64 tile, oc=40) ---------------------------
__global__ void gemm2_kernel(const float* __restrict__ Wl, const float* __restrict__ bl,
                             const float* __restrict__ Wr, const float* __restrict__ br, int n) {
    __shared__ float As[64][65];
    __shared__ float Bs[64][64];
    const float* W    = (blockIdx.y == 0) ? Wl : Wr;
    const float* bias = (blockIdx.y == 0) ? bl : br;
    float* C          = (blockIdx.y == 0) ? g_xl2 : g_xr2;
    const float* A = g_h1;
    const int oc = OUTF;
    int bRow = blockIdx.x * 64;
    int tid = threadIdx.x;
    int tx = tid & 15, ty = tid >> 4;
    float acc[4][4];
    #pragma unroll
    for (int i = 0; i < 4; i++)
        #pragma unroll
        for (int j = 0; j < 4; j++) acc[i][j] = 0.f;

    for (int kt = 0; kt < 128; kt += 64) {
        #pragma unroll
        for (int i = 0; i < 16; i++) {
            int idx = tid + 256 * i;
            int r = idx >> 6, c = idx & 63;
            int gr = bRow + r;
            As[r][c] = (gr < n) ? A[(size_t)gr * 128 + kt + c] : 0.f;
        }
        #pragma unroll
        for (int i = 0; i < 16; i++) {
            int idx = tid + 256 * i;
            int r = idx >> 6, c = idx & 63;
            Bs[r][c] = (c < oc) ? W[(size_t)(kt + r) * oc + c] : 0.f;
        }
        __syncthreads();
        #pragma unroll
        for (int k = 0; k < 64; k++) {
            float a[4], b[4];
            #pragma unroll
            for (int i = 0; i < 4; i++) a[i] = As[ty + 16 * i][k];
            #pragma unroll
            for (int j = 0; j < 4; j++) b[j] = Bs[k][tx + 16 * j];
            #pragma unroll
            for (int i = 0; i < 4; i++)
                #pragma unroll
                for (int j = 0; j < 4; j++) acc[i][j] += a[i] * b[j];
        }
        __syncthreads();
    }
    #pragma unroll
    for (int i = 0; i < 4; i++) {
        int gr = bRow + ty + 16 * i;
        if (gr >= n) continue;
        #pragma unroll
        for (int j = 0; j < 4; j++) {
            int gc = tx + 16 * j;
            if (gc < oc) C[(size_t)gr * oc + gc] = acc[i][j] + bias[gc];
        }
    }
}

// ------- layer-1 fused: score + softmax + aggregate + bias + LN + ELU --------
__global__ void agg1_kernel(const float* __restrict__ att1,
                            const float* __restrict__ b1,
                            const float* __restrict__ g1,
                            const float* __restrict__ be1, int n) {
    const unsigned full = 0xffffffffu;
    int node = (blockIdx.x * blockDim.x + threadIdx.x) >> 5;
    int lane = threadIdx.x & 31;
    if (node >= n) return;
    int beg = __ldg(&g_rowptr[node]), end = __ldg(&g_rowptr[node + 1]);

    float4 xr = *(const float4*)(g_xr1 + (size_t)node * D1 + lane * 4);
    float4 w  = *(const float4*)(att1 + lane * 4);

    // pass 1: scores per edge (whole warp), store e, track per-head max
    float mloc = -1e30f;
    int sNext = (beg < end) ? __ldg(&g_csrc[beg]) : 0;
    for (int p = beg; p < end; p++) {
        int s = sNext;
        if (p + 1 < end) sNext = __ldg(&g_csrc[p + 1]);
        float4 a = __ldg((const float4*)(g_xl1 + (size_t)s * D1 + lane * 4));
        float e = lrelu(a.x + xr.x) * w.x + lrelu(a.y + xr.y) * w.y +
                  lrelu(a.z + xr.z) * w.z + lrelu(a.w + xr.w) * w.w;
        e += __shfl_down_sync(full, e, 4, 8);
        e += __shfl_down_sync(full, e, 2, 8);
        e += __shfl_down_sync(full, e, 1, 8);
        if ((lane & 7) == 0) {
            g_e1[(size_t)p * 4 + (lane >> 3)] = e;
            mloc = fmaxf(mloc, e);
        }
    }
    __syncwarp();
    float m0 = __shfl_sync(full, mloc, 0);
    float m1 = __shfl_sync(full, mloc, 8);
    float m2 = __shfl_sync(full, mloc, 16);
    float m3 = __shfl_sync(full, mloc, 24);

    // pass 2: exp + sum, writeback exp
    float s0 = 0.f, s1 = 0.f, s2 = 0.f, s3 = 0.f;
    for (int p = beg + lane; p < end; p += 32) {
        float4 ev = *(const float4*)(g_e1 + (size_t)p * 4);
        ev.x = __expf(ev.x - m0); ev.y = __expf(ev.y - m1);
        ev.z = __expf(ev.z - m2); ev.w = __expf(ev.w - m3);
        s0 += ev.x; s1 += ev.y; s2 += ev.z; s3 += ev.w;
        *(float4*)(g_e1 + (size_t)p * 4) = ev;
    }
    #pragma unroll
    for (int off = 16; off > 0; off >>= 1) {
        s0 += __shfl_xor_sync(full, s0, off);
        s1 += __shfl_xor_sync(full, s1, off);
        s2 += __shfl_xor_sync(full, s2, off);
        s3 += __shfl_xor_sync(full, s3, off);
    }
    int h = lane >> 3;
    float sh = (h == 0) ? s0 : (h == 1) ? s1 : (h == 2) ? s2 : s3;
    float inv = 1.f / (sh + 1e-16f);

    // pass 3: weighted aggregation (prefetch src index one iteration ahead)
    float4 acc = make_float4(0.f, 0.f, 0.f, 0.f);
    sNext = (beg < end) ? __ldg(&g_csrc[beg]) : 0;
    for (int p = beg; p < end; p++) {
        int s = sNext;
        if (p + 1 < end) sNext = __ldg(&g_csrc[p + 1]);
        float alpha = g_e1[(size_t)p * 4 + h] * inv;
        float4 v = __ldg((const float4*)(g_xl1 + (size_t)s * D1 + lane * 4));
        acc.x += alpha * v.x; acc.y += alpha * v.y;
        acc.z += alpha * v.z; acc.w += alpha * v.w;
    }
    float4 bb = *(const float4*)(b1 + lane * 4);
    acc.x += bb.x; acc.y += bb.y; acc.z += bb.z; acc.w += bb.w;

    // LayerNorm over 128 features (warp-wide) + ELU
    float psum = acc.x + acc.y + acc.z + acc.w;
    float psq  = acc.x * acc.x + acc.y * acc.y + acc.z * acc.z + acc.w * acc.w;
    #pragma unroll
    for (int off = 16; off > 0; off >>= 1) {
        psum += __shfl_xor_sync(full, psum, off);
        psq  += __shfl_xor_sync(full, psq,  off);
    }
    float mean = psum * (1.f / 128.f);
    float var  = psq * (1.f / 128.f) - mean * mean;
    float rstd = rsqrtf(var + LN_EPS);
    float4 gg = *(const float4*)(g1  + lane * 4);
    float4 ee = *(const float4*)(be1 + lane * 4);
    float y0 = (acc.x - mean) * rstd * gg.x + ee.x;
    float y1 = (acc.y - mean) * rstd * gg.y + ee.y;
    float y2 = (acc.z - mean) * rstd * gg.z + ee.z;
    float y3 = (acc.w - mean) * rstd * gg.w + ee.w;
    y0 = y0 > 0.f ? y0 : expm1f(y0);
    y1 = y1 > 0.f ? y1 : expm1f(y1);
    y2 = y2 > 0.f ? y2 : expm1f(y2);
    y3 = y3 > 0.f ? y3 : expm1f(y3);
    *(float4*)(g_h1 + (size_t)node * D1 + lane * 4) = make_float4(y0, y1, y2, y3);
}

// ------- layer-2 fused: score + softmax + aggregate -> output ----------------
__global__ void agg2_kernel(const float* __restrict__ att2,
                            const float* __restrict__ b2,
                            float* __restrict__ out, int n) {
    const unsigned full = 0xffffffffu;
    int node = (blockIdx.x * blockDim.x + threadIdx.x) >> 5;
    int lane = threadIdx.x & 31;
    if (node >= n) return;
    int beg = __ldg(&g_rowptr[node]), end = __ldg(&g_rowptr[node + 1]);

    float xra = g_xr2[(size_t)node * OUTF + lane];
    float xrb = (lane < 8) ? g_xr2[(size_t)node * OUTF + 32 + lane] : 0.f;
    float wa = att2[lane];
    float wb = (lane < 8) ? att2[32 + lane] : 0.f;

    // pass 1: scores
    float m = -1e30f;
    int sNext = (beg < end) ? __ldg(&g_csrc[beg]) : 0;
    for (int p = beg; p < end; p++) {
        int s = sNext;
        if (p + 1 < end) sNext = __ldg(&g_csrc[p + 1]);
        float e = lrelu(__ldg(&g_xl2[(size_t)s * OUTF + lane]) + xra) * wa;
        if (lane < 8) e += lrelu(__ldg(&g_xl2[(size_t)s * OUTF + 32 + lane]) + xrb) * wb;
        #pragma unroll
        for (int off = 16; off > 0; off >>= 1) e += __shfl_xor_sync(full, e, off);
        if (lane == 0) g_e2[p] = e;
        m = fmaxf(m, e);
    }
    __syncwarp();

    // pass 2: exp + sum, writeback
    float s = 0.f;
    for (int p = beg + lane; p < end; p += 32) {
        float v = __expf(g_e2[p] - m);
        g_e2[p] = v;
        s += v;
    }
    #pragma unroll
    for (int off = 16; off > 0; off >>= 1) s += __shfl_xor_sync(full, s, off);
    float inv = 1.f / (s + 1e-16f);

    // pass 3: aggregate (prefetch src index)
    float acc0 = 0.f, acc1 = 0.f;
    sNext = (beg < end) ? __ldg(&g_csrc[beg]) : 0;
    for (int p = beg; p < end; p++) {
        int sr = sNext;
        if (p + 1 < end) sNext = __ldg(&g_csrc[p + 1]);
        float alpha = g_e2[p] * inv;
        acc0 += alpha * __ldg(&g_xl2[(size_t)sr * OUTF + lane]);
        if (lane < 8) acc1 += alpha * __ldg(&g_xl2[(size_t)sr * OUTF + 32 + lane]);
    }
    out[(size_t)node * OUTF + lane] = acc0 + b2[lane];
    if (lane < 8) out[(size_t)node * OUTF + 32 + lane] = acc1 + b2[32 + lane];
}

// ---------------- launch -----------------------------------------------------
extern "C" void kernel_launch(void* const* d_in, const int* in_sizes, int n_in,
                              void* d_out, int out_size) {
    const float* x    = (const float*)d_in[0];
    const void*  eidx = d_in[1];
    const float* Wl1  = (const float*)d_in[2];
    const float* bl1  = (const float*)d_in[3];
    const float* Wr1  = (const float*)d_in[4];
    const float* br1  = (const float*)d_in[5];
    const float* att1 = (const float*)d_in[6];
    const float* b1   = (const float*)d_in[7];
    const float* g1   = (const float*)d_in[8];
    const float* be1  = (const float*)d_in[9];
    const float* Wl2  = (const float*)d_in[10];
    const float* bl2  = (const float*)d_in[11];
    const float* Wr2  = (const float*)d_in[12];
    const float* br2  = (const float*)d_in[13];
    const float* att2 = (const float*)d_in[14];
    const float* b2   = (const float*)d_in[15];
    float* out = (float*)d_out;

    int n = in_sizes[0] / 128;
    int E = in_sizes[1] / 2;
    int nb = (n + 255) / 256;

    // CSR build
    detect_kernel<<<1, 32>>>((const int*)eidx);
    zero_cnt_kernel<<<nb, 256>>>(n);
    convert_hist_kernel<<<(E + 255) / 256, 256>>>(eidx, E);
    scan_a_kernel<<<nb, 256>>>(n);
    scan_b_kernel<<<1, 256>>>(nb);
    scan_c_kernel<<<nb, 256>>>(n, E);
    scatter_kernel<<<(E + 255) / 256, 256>>>(E);

    // layer 1
    {
        dim3 grid((n + 127) / 128, 2);
        gemm1_kernel<<<grid, 256>>>(x, Wl1, bl1, Wr1, br1, n);
    }
    agg1_kernel<<<(n + 7) / 8, 256>>>(att1, b1, g1, be1, n);

    // layer 2
    {
        dim3 grid((n + 63) / 64, 2);
        gemm2_kernel<<<grid, 256>>>(Wl2, bl2, Wr2, br2, n);
    }
    agg2_kernel<<<(n + 7) / 8, 256>>>(att2, b2, out, n);
}

// round 7
// speedup vs baseline: 1.4352x; 1.0432x over previous
#include <cuda_runtime.h>
#include <math.h>

// Problem constants (fixed by dataset)
#define NMAX 50000
#define EMAX 800000
#define D1   128     // heads*hid = 4*32
#define HEADS 4
#define HID  32
#define OUTF 40
#define LN_EPS 1e-5f

// ---------------- scratch (device globals; no allocation allowed) ------------
__device__ float g_xl1[NMAX * D1];
__device__ float g_xr1[NMAX * D1];
__device__ float g_h1 [NMAX * D1];
__device__ float g_xl2[NMAX * OUTF];
__device__ float g_xr2[NMAX * OUTF];
__device__ int   g_src[EMAX];
__device__ int   g_tgt[EMAX];
__device__ int   g_csrc[EMAX];         // src per CSR slot
__device__ int   g_cnt[NMAX];
__device__ int   g_rowptr[NMAX + 1];
__device__ int   g_cursor[NMAX];
__device__ int   g_bsum[256];
__device__ int   g_boff[256];
__device__ int   g_is64;

__device__ __forceinline__ float lrelu(float x) { return x > 0.f ? x : 0.2f * x; }

// packed f32x2 helpers
#define FMA_F32X2(d, a, b) \
    asm("fma.rn.f32x2 %0, %1, %2, %0;" : "+l"(d) : "l"(a), "l"(b))
#define UNPACK_F32X2(lo, hi, in) \
    asm("mov.b64 {%0, %1}, %2;" : "=f"(lo), "=f"(hi) : "l"(in))

// ---------------- edge index dtype detection ---------------------------------
__global__ void detect_kernel(const int* raw) {
    if (threadIdx.x == 0) {
        int ok = 1;
        #pragma unroll
        for (int i = 0; i < 8; i++)
            if (raw[2 * i + 1] != 0) ok = 0;   // int64 < 2^31 -> hi words zero
        g_is64 = ok;
    }
}

__global__ void zero_cnt_kernel(int n) {
    int i = blockIdx.x * blockDim.x + threadIdx.x;
    if (i < n) g_cnt[i] = 0;
}

// convert + histogram in one pass
__global__ void convert_hist_kernel(const void* raw, int E) {
    int i = blockIdx.x * blockDim.x + threadIdx.x;
    if (i >= E) return;
    int s, t;
    if (g_is64) {
        const long long* p = (const long long*)raw;
        s = (int)p[i]; t = (int)p[E + i];
    } else {
        const int* p = (const int*)raw;
        s = p[i]; t = p[E + i];
    }
    g_src[i] = s;
    g_tgt[i] = t;
    atomicAdd(&g_cnt[t], 1);
}

// ---------------- parallel exclusive scan (3 kernels) ------------------------
__device__ __forceinline__ int excl_scan_block(int v, int* wsum, int& total) {
    const unsigned full = 0xffffffffu;
    int lane = threadIdx.x & 31, w = threadIdx.x >> 5;
    int x = v;
    #pragma unroll
    for (int off = 1; off < 32; off <<= 1) {
        int t = __shfl_up_sync(full, x, off);
        if (lane >= off) x += t;
    }
    if (lane == 31) wsum[w] = x;
    __syncthreads();
    if (w == 0) {
        int s = (lane < 8) ? wsum[lane] : 0;
        #pragma unroll
        for (int off = 1; off < 8; off <<= 1) {
            int t = __shfl_up_sync(full, s, off);
            if (lane >= off) s += t;
        }
        if (lane < 8) wsum[lane] = s;
    }
    __syncthreads();
    int base = (w > 0) ? wsum[w - 1] : 0;
    total = wsum[7];
    return base + x - v;
}

__global__ void scan_a_kernel(int n) {
    __shared__ int wsum[8];
    int i = blockIdx.x * 256 + threadIdx.x;
    int v = (i < n) ? g_cnt[i] : 0;
    int total;
    int ex = excl_scan_block(v, wsum, total);
    if (i < n) g_rowptr[i] = ex;
    if (threadIdx.x == 0) g_bsum[blockIdx.x] = total;
}

__global__ void scan_b_kernel(int nb) {
    __shared__ int wsum[8];
    int b = threadIdx.x;
    int v = (b < nb) ? g_bsum[b] : 0;
    int total;
    int ex = excl_scan_block(v, wsum, total);
    if (b < nb) g_boff[b] = ex;
}

__global__ void scan_c_kernel(int n, int E) {
    int i = blockIdx.x * 256 + threadIdx.x;
    if (i < n) {
        int rp = g_rowptr[i] + g_boff[blockIdx.x];
        g_rowptr[i] = rp;
        g_cursor[i] = rp;
    }
    if (i == 0) g_rowptr[n] = E;
}

__global__ void scatter_kernel(int E) {
    int i = blockIdx.x * blockDim.x + threadIdx.x;
    if (i >= E) return;
    int t = g_tgt[i];
    int pos = atomicAdd(&g_cursor[t], 1);
    g_csrc[pos] = g_src[i];
}

// ---------------- layer-1 GEMM: 128x128 tile, packed f32x2 FMA ---------------
// C = A[n,128] @ W[128,128] + bias ; grid.y selects (Wl->xl1) / (Wr->xr1)
// Per thread: 8 rows (ty*8+i) x 8 cols (tx+16*j), f32x2 accumulators over
// k-pairs: .lo accumulates even-k products, .hi odd-k. Final = lo+hi.
__global__ __launch_bounds__(256, 1) void gemm1_kernel(
        const float* __restrict__ x,
        const float* __restrict__ Wl, const float* __restrict__ bl,
        const float* __restrict__ Wr, const float* __restrict__ br, int n) {
    __shared__ float  As[128][32];     // A chunk: row-major, 32 k per chunk
    __shared__ float2 Bst[16][128];    // B chunk: [k-pair][col] = (W[2kp][c], W[2kp+1][c])
    const float* W    = (blockIdx.y == 0) ? Wl : Wr;
    const float* bias = (blockIdx.y == 0) ? bl : br;
    float* C          = (blockIdx.y == 0) ? g_xl1 : g_xr1;
    int bRow = blockIdx.x * 128;
    int tid = threadIdx.x;
    int tx = tid & 15;                 // cols tx + 16*j
    int ty = tid >> 4;                 // rows ty*8 + i
    unsigned long long acc[8][8];
    #pragma unroll
    for (int i = 0; i < 8; i++)
        #pragma unroll
        for (int j = 0; j < 8; j++) acc[i][j] = 0ull;

    for (int kt = 0; kt < 128; kt += 32) {
        // A chunk: 128 rows x 32 floats (8 float4 per row -> 1024 slots)
        #pragma unroll
        for (int it = 0; it < 4; it++) {
            int slot = tid + it * 256;
            int r  = slot >> 3;            // 0..127
            int c4 = (slot & 7) * 4;       // 0..28
            int gr = bRow + r;
            float4 v = (gr < n) ? *(const float4*)(x + (size_t)gr * 128 + kt + c4)
                                : make_float4(0.f, 0.f, 0.f, 0.f);
            *(float4*)&As[r][c4] = v;
        }
        // B chunk: 16 k-pairs x 128 cols (two W rows packed into float2)
        #pragma unroll
        for (int it = 0; it < 2; it++) {
            int slot = tid + it * 256;     // 0..511
            int kp = slot >> 5;            // 0..15
            int c4 = (slot & 31) * 4;      // 0..124
            float4 e0 = *(const float4*)(W + (size_t)(kt + 2 * kp)     * 128 + c4);
            float4 e1 = *(const float4*)(W + (size_t)(kt + 2 * kp + 1) * 128 + c4);
            Bst[kp][c4 + 0] = make_float2(e0.x, e1.x);
            Bst[kp][c4 + 1] = make_float2(e0.y, e1.y);
            Bst[kp][c4 + 2] = make_float2(e0.z, e1.z);
            Bst[kp][c4 + 3] = make_float2(e0.w, e1.w);
        }
        __syncthreads();
        #pragma unroll 4
        for (int kp = 0; kp < 16; kp++) {
            unsigned long long a2[8], b2[8];
            #pragma unroll
            for (int i = 0; i < 8; i++)
                a2[i] = *(const unsigned long long*)&As[ty * 8 + i][2 * kp];
            #pragma unroll
            for (int j = 0; j < 8; j++)
                b2[j] = *(const unsigned long long*)&Bst[kp][tx + 16 * j];
            #pragma unroll
            for (int i = 0; i < 8; i++)
                #pragma unroll
                for (int j = 0; j < 8; j++)
                    FMA_F32X2(acc[i][j], a2[i], b2[j]);
        }
        __syncthreads();
    }
    // epilogue
    float bs[8];
    #pragma unroll
    for (int j = 0; j < 8; j++) bs[j] = bias[tx + 16 * j];
    #pragma unroll
    for (int i = 0; i < 8; i++) {
        int gr = bRow + ty * 8 + i;
        if (gr >= n) continue;
        #pragma unroll
        for (int j = 0; j < 8; j++) {
            float lo, hi;
            UNPACK_F32X2(lo, hi, acc[i][j]);
            C[(size_t)gr * 128 + tx + 16 * j] = lo + hi + bs[j];
        }
    }
}

// ---------------- layer-2 GEMM (64x64 tile, oc=40) ---------------------------
__global__ void gemm2_kernel(const float* __restrict__ Wl, const float* __restrict__ bl,
                             const float* __restrict__ Wr, const float* __restrict__ br, int n) {
    __shared__ float As[64][65];
    __shared__ float Bs[64][64];
    const float* W    = (blockIdx.y == 0) ? Wl : Wr;
    const float* bias = (blockIdx.y == 0) ? bl : br;
    float* C          = (blockIdx.y == 0) ? g_xl2 : g_xr2;
    const float* A = g_h1;
    const int oc = OUTF;
    int bRow = blockIdx.x * 64;
    int tid = threadIdx.x;
    int tx = tid & 15, ty = tid >> 4;
    float acc[4][4];
    #pragma unroll
    for (int i = 0; i < 4; i++)
        #pragma unroll
        for (int j = 0; j < 4; j++) acc[i][j] = 0.f;

    for (int kt = 0; kt < 128; kt += 64) {
        #pragma unroll
        for (int i = 0; i < 16; i++) {
            int idx = tid + 256 * i;
            int r = idx >> 6, c = idx & 63;
            int gr = bRow + r;
            As[r][c] = (gr < n) ? A[(size_t)gr * 128 + kt + c] : 0.f;
        }
        #pragma unroll
        for (int i = 0; i < 16; i++) {
            int idx = tid + 256 * i;
            int r = idx >> 6, c = idx & 63;
            Bs[r][c] = (c < oc) ? W[(size_t)(kt + r) * oc + c] : 0.f;
        }
        __syncthreads();
        #pragma unroll
        for (int k = 0; k < 64; k++) {
            float a[4], b[4];
            #pragma unroll
            for (int i = 0; i < 4; i++) a[i] = As[ty + 16 * i][k];
            #pragma unroll
            for (int j = 0; j < 4; j++) b[j] = Bs[k][tx + 16 * j];
            #pragma unroll
            for (int i = 0; i < 4; i++)
                #pragma unroll
                for (int j = 0; j < 4; j++) acc[i][j] += a[i] * b[j];
        }
        __syncthreads();
    }
    #pragma unroll
    for (int i = 0; i < 4; i++) {
        int gr = bRow + ty + 16 * i;
        if (gr >= n) continue;
        #pragma unroll
        for (int j = 0; j < 4; j++) {
            int gc = tx + 16 * j;
            if (gc < oc) C[(size_t)gr * oc + gc] = acc[i][j] + bias[gc];
        }
    }
}

// ------- layer-1 fused: score + ONLINE softmax + aggregate + LN + ELU --------
// Single gather pass over xl1[src]; no edge-score scratch traffic at all.
__global__ void agg1_kernel(const float* __restrict__ att1,
                            const float* __restrict__ b1,
                            const float* __restrict__ g1,
                            const float* __restrict__ be1, int n) {
    const unsigned full = 0xffffffffu;
    int node = (blockIdx.x * blockDim.x + threadIdx.x) >> 5;
    int lane = threadIdx.x & 31;
    if (node >= n) return;
    int beg = __ldg(&g_rowptr[node]), end = __ldg(&g_rowptr[node + 1]);

    float4 xr = *(const float4*)(g_xr1 + (size_t)node * D1 + lane * 4);
    float4 w  = *(const float4*)(att1 + lane * 4);

    float m = -1e30f;      // running per-head max (replicated in 8-lane group)
    float denom = 0.f;     // running per-head sum of exp
    float4 acc = make_float4(0.f, 0.f, 0.f, 0.f);

    int sNext = (beg < end) ? __ldg(&g_csrc[beg]) : 0;
    for (int p = beg; p < end; p++) {
        int s = sNext;
        if (p + 1 < end) sNext = __ldg(&g_csrc[p + 1]);
        float4 a = __ldg((const float4*)(g_xl1 + (size_t)s * D1 + lane * 4));
        float e = lrelu(a.x + xr.x) * w.x + lrelu(a.y + xr.y) * w.y +
                  lrelu(a.z + xr.z) * w.z + lrelu(a.w + xr.w) * w.w;
        // butterfly within 8-lane head group: all lanes get the head score
        e += __shfl_xor_sync(full, e, 4);
        e += __shfl_xor_sync(full, e, 2);
        e += __shfl_xor_sync(full, e, 1);
        float mnew  = fmaxf(m, e);
        float scale = __expf(m - mnew);   // first iter: exp(-inf) = 0
        float wgt   = __expf(e - mnew);
        denom = denom * scale + wgt;
        acc.x = acc.x * scale + wgt * a.x;
        acc.y = acc.y * scale + wgt * a.y;
        acc.z = acc.z * scale + wgt * a.z;
        acc.w = acc.w * scale + wgt * a.w;
        m = mnew;
    }
    float inv = 1.f / (denom + 1e-16f);
    float4 bb = *(const float4*)(b1 + lane * 4);
    acc.x = acc.x * inv + bb.x; acc.y = acc.y * inv + bb.y;
    acc.z = acc.z * inv + bb.z; acc.w = acc.w * inv + bb.w;

    // LayerNorm over 128 features (warp-wide) + ELU
    float psum = acc.x + acc.y + acc.z + acc.w;
    float psq  = acc.x * acc.x + acc.y * acc.y + acc.z * acc.z + acc.w * acc.w;
    #pragma unroll
    for (int off = 16; off > 0; off >>= 1) {
        psum += __shfl_xor_sync(full, psum, off);
        psq  += __shfl_xor_sync(full, psq,  off);
    }
    float mean = psum * (1.f / 128.f);
    float var  = psq * (1.f / 128.f) - mean * mean;
    float rstd = rsqrtf(var + LN_EPS);
    float4 gg = *(const float4*)(g1  + lane * 4);
    float4 ee = *(const float4*)(be1 + lane * 4);
    float y0 = (acc.x - mean) * rstd * gg.x + ee.x;
    float y1 = (acc.y - mean) * rstd * gg.y + ee.y;
    float y2 = (acc.z - mean) * rstd * gg.z + ee.z;
    float y3 = (acc.w - mean) * rstd * gg.w + ee.w;
    y0 = y0 > 0.f ? y0 : expm1f(y0);
    y1 = y1 > 0.f ? y1 : expm1f(y1);
    y2 = y2 > 0.f ? y2 : expm1f(y2);
    y3 = y3 > 0.f ? y3 : expm1f(y3);
    *(float4*)(g_h1 + (size_t)node * D1 + lane * 4) = make_float4(y0, y1, y2, y3);
}

// ------- layer-2 fused: score + ONLINE softmax + aggregate -> output ---------
__global__ void agg2_kernel(const float* __restrict__ att2,
                            const float* __restrict__ b2,
                            float* __restrict__ out, int n) {
    const unsigned full = 0xffffffffu;
    int node = (blockIdx.x * blockDim.x + threadIdx.x) >> 5;
    int lane = threadIdx.x & 31;
    if (node >= n) return;
    int beg = __ldg(&g_rowptr[node]), end = __ldg(&g_rowptr[node + 1]);

    float xra = g_xr2[(size_t)node * OUTF + lane];
    float xrb = (lane < 8) ? g_xr2[(size_t)node * OUTF + 32 + lane] : 0.f;
    float wa = att2[lane];
    float wb = (lane < 8) ? att2[32 + lane] : 0.f;

    float m = -1e30f, denom = 0.f;
    float acc0 = 0.f, acc1 = 0.f;

    int sNext = (beg < end) ? __ldg(&g_csrc[beg]) : 0;
    for (int p = beg; p < end; p++) {
        int s = sNext;
        if (p + 1 < end) sNext = __ldg(&g_csrc[p + 1]);
        float va = __ldg(&g_xl2[(size_t)s * OUTF + lane]);
        float vb = (lane < 8) ? __ldg(&g_xl2[(size_t)s * OUTF + 32 + lane]) : 0.f;
        float e = lrelu(va + xra) * wa + ((lane < 8) ? lrelu(vb + xrb) * wb : 0.f);
        #pragma unroll
        for (int off = 16; off > 0; off >>= 1) e += __shfl_xor_sync(full, e, off);
        float mnew  = fmaxf(m, e);
        float scale = __expf(m - mnew);
        float wgt   = __expf(e - mnew);
        denom = denom * scale + wgt;
        acc0 = acc0 * scale + wgt * va;
        acc1 = acc1 * scale + wgt * vb;
        m = mnew;
    }
    float inv = 1.f / (denom + 1e-16f);
    out[(size_t)node * OUTF + lane] = acc0 * inv + b2[lane];
    if (lane < 8) out[(size_t)node * OUTF + 32 + lane] = acc1 * inv + b2[32 + lane];
}

// ---------------- launch -----------------------------------------------------
extern "C" void kernel_launch(void* const* d_in, const int* in_sizes, int n_in,
                              void* d_out, int out_size) {
    const float* x    = (const float*)d_in[0];
    const void*  eidx = d_in[1];
    const float* Wl1  = (const float*)d_in[2];
    const float* bl1  = (const float*)d_in[3];
    const float* Wr1  = (const float*)d_in[4];
    const float* br1  = (const float*)d_in[5];
    const float* att1 = (const float*)d_in[6];
    const float* b1   = (const float*)d_in[7];
    const float* g1   = (const float*)d_in[8];
    const float* be1  = (const float*)d_in[9];
    const float* Wl2  = (const float*)d_in[10];
    const float* bl2  = (const float*)d_in[11];
    const float* Wr2  = (const float*)d_in[12];
    const float* br2  = (const float*)d_in[13];
    const float* att2 = (const float*)d_in[14];
    const float* b2   = (const float*)d_in[15];
    float* out = (float*)d_out;

    int n = in_sizes[0] / 128;
    int E = in_sizes[1] / 2;
    int nb = (n + 255) / 256;

    // CSR build
    detect_kernel<<<1, 32>>>((const int*)eidx);
    zero_cnt_kernel<<<nb, 256>>>(n);
    convert_hist_kernel<<<(E + 255) / 256, 256>>>(eidx, E);
    scan_a_kernel<<<nb, 256>>>(n);
    scan_b_kernel<<<1, 256>>>(nb);
    scan_c_kernel<<<nb, 256>>>(n, E);
    scatter_kernel<<<(E + 255) / 256, 256>>>(E);

    // layer 1
    {
        dim3 grid((n + 127) / 128, 2);
        gemm1_kernel<<<grid, 256>>>(x, Wl1, bl1, Wr1, br1, n);
    }
    agg1_kernel<<<(n + 7) / 8, 256>>>(att1, b1, g1, be1, n);

    // layer 2
    {
        dim3 grid((n + 63) / 64, 2);
        gemm2_kernel<<<grid, 256>>>(Wl2, bl2, Wr2, br2, n);
    }
    agg2_kernel<<<(n + 7) / 8, 256>>>(att2, b2, out, n);
}

// round 10
// speedup vs baseline: 1.4476x; 1.0087x over previous
#include <cuda_runtime.h>
#include <math.h>

// Problem constants (fixed by dataset)
#define NMAX 50000
#define EMAX 800000
#define D1   128     // heads*hid = 4*32
#define HEADS 4
#define HID  32
#define OUTF 40
#define LN_EPS 1e-5f

// ---------------- scratch (device globals; no allocation allowed) ------------
__device__ float g_xl1[NMAX * D1];
__device__ float g_xr1[NMAX * D1];
__device__ float g_h1 [NMAX * D1];
__device__ float g_xl2[NMAX * OUTF];
__device__ float g_xr2[NMAX * OUTF];
__device__ int   g_src[EMAX];
__device__ int   g_tgt[EMAX];
__device__ int   g_csrc[EMAX];         // src per CSR slot
__device__ int   g_cnt[NMAX];
__device__ int   g_rowptr[NMAX + 1];
__device__ int   g_cursor[NMAX];
__device__ int   g_bsum[256];
__device__ int   g_boff[256];
__device__ int   g_is64;

__device__ __forceinline__ float lrelu(float x) { return x > 0.f ? x : 0.2f * x; }

// ---------------- edge index dtype detection ---------------------------------
__global__ void detect_kernel(const int* raw) {
    if (threadIdx.x == 0) {
        int ok = 1;
        #pragma unroll
        for (int i = 0; i < 8; i++)
            if (raw[2 * i + 1] != 0) ok = 0;   // int64 < 2^31 -> hi words zero
        g_is64 = ok;
    }
}

__global__ void zero_cnt_kernel(int n) {
    int i = blockIdx.x * blockDim.x + threadIdx.x;
    if (i < n) g_cnt[i] = 0;
}

// convert + histogram in one pass
__global__ void convert_hist_kernel(const void* raw, int E) {
    int i = blockIdx.x * blockDim.x + threadIdx.x;
    if (i >= E) return;
    int s, t;
    if (g_is64) {
        const long long* p = (const long long*)raw;
        s = (int)p[i]; t = (int)p[E + i];
    } else {
        const int* p = (const int*)raw;
        s = p[i]; t = p[E + i];
    }
    g_src[i] = s;
    g_tgt[i] = t;
    atomicAdd(&g_cnt[t], 1);
}

// ---------------- layer-1 GEMM: 128x128 tile, 8x8/thread, fp32 ---------------
// (4th launch in the stream -> this is what ncu profiles)
__global__ __launch_bounds__(256, 2) void gemm1_kernel(
        const float* __restrict__ x,
        const float* __restrict__ Wl, const float* __restrict__ bl,
        const float* __restrict__ Wr, const float* __restrict__ br, int n) {
    __shared__ float Ast[32][132];   // transposed A tile: Ast[k][row]
    __shared__ float Bs[32][128];
    const float* W    = (blockIdx.y == 0) ? Wl : Wr;
    const float* bias = (blockIdx.y == 0) ? bl : br;
    float* C          = (blockIdx.y == 0) ? g_xl1 : g_xr1;
    int bRow = blockIdx.x * 128;
    int tid = threadIdx.x;
    int tx = tid & 15, ty = tid >> 4;
    float acc[8][8];
    #pragma unroll
    for (int i = 0; i < 8; i++)
        #pragma unroll
        for (int j = 0; j < 8; j++) acc[i][j] = 0.f;

    for (int kt = 0; kt < 128; kt += 32) {
        #pragma unroll
        for (int it = 0; it < 4; it++) {
            int slot = tid + it * 256;       // 0..1023
            int r = slot >> 3;               // 0..127
            int k4 = (slot & 7) * 4;         // 0..28
            int gr = bRow + r;
            float4 av = (gr < n) ? *(const float4*)(x + (size_t)gr * 128 + kt + k4)
                                 : make_float4(0.f, 0.f, 0.f, 0.f);
            Ast[k4 + 0][r] = av.x; Ast[k4 + 1][r] = av.y;
            Ast[k4 + 2][r] = av.z; Ast[k4 + 3][r] = av.w;
        }
        #pragma unroll
        for (int it = 0; it < 4; it++) {
            int slot = tid + it * 256;
            int k = slot >> 5;               // 0..31
            int c4 = (slot & 31) * 4;        // 0..124
            *(float4*)(&Bs[k][c4]) = *(const float4*)(W + (size_t)(kt + k) * 128 + c4);
        }
        __syncthreads();
        #pragma unroll
        for (int k = 0; k < 32; k++) {
            float4 a0 = *(const float4*)(&Ast[k][ty * 8]);
            float4 a1 = *(const float4*)(&Ast[k][ty * 8 + 4]);
            float4 b0 = *(const float4*)(&Bs[k][tx * 8]);
            float4 b1 = *(const float4*)(&Bs[k][tx * 8 + 4]);
            float a[8] = {a0.x, a0.y, a0.z, a0.w, a1.x, a1.y, a1.z, a1.w};
            float b[8] = {b0.x, b0.y, b0.z, b0.w, b1.x, b1.y, b1.z, b1.w};
            #pragma unroll
            for (int i = 0; i < 8; i++)
                #pragma unroll
                for (int j = 0; j < 8; j++) acc[i][j] += a[i] * b[j];
        }
        __syncthreads();
    }
    #pragma unroll
    for (int i = 0; i < 8; i++) {
        int gr = bRow + ty * 8 + i;
        if (gr >= n) continue;
        float4 o0, o1;
        o0.x = acc[i][0] + bias[tx * 8 + 0]; o0.y = acc[i][1] + bias[tx * 8 + 1];
        o0.z = acc[i][2] + bias[tx * 8 + 2]; o0.w = acc[i][3] + bias[tx * 8 + 3];
        o1.x = acc[i][4] + bias[tx * 8 + 4]; o1.y = acc[i][5] + bias[tx * 8 + 5];
        o1.z = acc[i][6] + bias[tx * 8 + 6]; o1.w = acc[i][7] + bias[tx * 8 + 7];
        *(float4*)(C + (size_t)gr * 128 + tx * 8)     = o0;
        *(float4*)(C + (size_t)gr * 128 + tx * 8 + 4) = o1;
    }
}

// ---------------- parallel exclusive scan (3 kernels) ------------------------
__device__ __forceinline__ int excl_scan_block(int v, int* wsum, int& total) {
    const unsigned full = 0xffffffffu;
    int lane = threadIdx.x & 31, w = threadIdx.x >> 5;
    int x = v;
    #pragma unroll
    for (int off = 1; off < 32; off <<= 1) {
        int t = __shfl_up_sync(full, x, off);
        if (lane >= off) x += t;
    }
    if (lane == 31) wsum[w] = x;
    __syncthreads();
    if (w == 0) {
        int s = (lane < 8) ? wsum[lane] : 0;
        #pragma unroll
        for (int off = 1; off < 8; off <<= 1) {
            int t = __shfl_up_sync(full, s, off);
            if (lane >= off) s += t;
        }
        if (lane < 8) wsum[lane] = s;
    }
    __syncthreads();
    int base = (w > 0) ? wsum[w - 1] : 0;
    total = wsum[7];
    return base + x - v;
}

__global__ void scan_a_kernel(int n) {
    __shared__ int wsum[8];
    int i = blockIdx.x * 256 + threadIdx.x;
    int v = (i < n) ? g_cnt[i] : 0;
    int total;
    int ex = excl_scan_block(v, wsum, total);
    if (i < n) g_rowptr[i] = ex;
    if (threadIdx.x == 0) g_bsum[blockIdx.x] = total;
}

__global__ void scan_b_kernel(int nb) {
    __shared__ int wsum[8];
    int b = threadIdx.x;
    int v = (b < nb) ? g_bsum[b] : 0;
    int total;
    int ex = excl_scan_block(v, wsum, total);
    if (b < nb) g_boff[b] = ex;
}

__global__ void scan_c_kernel(int n, int E) {
    int i = blockIdx.x * 256 + threadIdx.x;
    if (i < n) {
        int rp = g_rowptr[i] + g_boff[blockIdx.x];
        g_rowptr[i] = rp;
        g_cursor[i] = rp;
    }
    if (i == 0) g_rowptr[n] = E;
}

__global__ void scatter_kernel(int E) {
    int i = blockIdx.x * blockDim.x + threadIdx.x;
    if (i >= E) return;
    int t = g_tgt[i];
    int pos = atomicAdd(&g_cursor[t], 1);
    g_csrc[pos] = g_src[i];
}

// ---------------- layer-2 GEMM (64x64 tile, oc=40) ---------------------------
__global__ void gemm2_kernel(const float* __restrict__ Wl, const float* __restrict__ bl,
                             const float* __restrict__ Wr, const float* __restrict__ br, int n) {
    __shared__ float As[64][65];
    __shared__ float Bs[64][64];
    const float* W    = (blockIdx.y == 0) ? Wl : Wr;
    const float* bias = (blockIdx.y == 0) ? bl : br;
    float* C          = (blockIdx.y == 0) ? g_xl2 : g_xr2;
    const float* A = g_h1;
    const int oc = OUTF;
    int bRow = blockIdx.x * 64;
    int tid = threadIdx.x;
    int tx = tid & 15, ty = tid >> 4;
    float acc[4][4];
    #pragma unroll
    for (int i = 0; i < 4; i++)
        #pragma unroll
        for (int j = 0; j < 4; j++) acc[i][j] = 0.f;

    for (int kt = 0; kt < 128; kt += 64) {
        #pragma unroll
        for (int i = 0; i < 16; i++) {
            int idx = tid + 256 * i;
            int r = idx >> 6, c = idx & 63;
            int gr = bRow + r;
            As[r][c] = (gr < n) ? A[(size_t)gr * 128 + kt + c] : 0.f;
        }
        #pragma unroll
        for (int i = 0; i < 16; i++) {
            int idx = tid + 256 * i;
            int r = idx >> 6, c = idx & 63;
            Bs[r][c] = (c < oc) ? W[(size_t)(kt + r) * oc + c] : 0.f;
        }
        __syncthreads();
        #pragma unroll
        for (int k = 0; k < 64; k++) {
            float a[4], b[4];
            #pragma unroll
            for (int i = 0; i < 4; i++) a[i] = As[ty + 16 * i][k];
            #pragma unroll
            for (int j = 0; j < 4; j++) b[j] = Bs[k][tx + 16 * j];
            #pragma unroll
            for (int i = 0; i < 4; i++)
                #pragma unroll
                for (int j = 0; j < 4; j++) acc[i][j] += a[i] * b[j];
        }
        __syncthreads();
    }
    #pragma unroll
    for (int i = 0; i < 4; i++) {
        int gr = bRow + ty + 16 * i;
        if (gr >= n) continue;
        #pragma unroll
        for (int j = 0; j < 4; j++) {
            int gc = tx + 16 * j;
            if (gc < oc) C[(size_t)gr * oc + gc] = acc[i][j] + bias[gc];
        }
    }
}

// ------- layer-1 fused: score + ONLINE softmax + aggregate + LN + ELU --------
__global__ void agg1_kernel(const float* __restrict__ att1,
                            const float* __restrict__ b1,
                            const float* __restrict__ g1,
                            const float* __restrict__ be1, int n) {
    const unsigned full = 0xffffffffu;
    int node = (blockIdx.x * blockDim.x + threadIdx.x) >> 5;
    int lane = threadIdx.x & 31;
    if (node >= n) return;
    int beg = __ldg(&g_rowptr[node]), end = __ldg(&g_rowptr[node + 1]);

    float4 xr = *(const float4*)(g_xr1 + (size_t)node * D1 + lane * 4);
    float4 w  = *(const float4*)(att1 + lane * 4);

    float m = -1e30f;      // running per-head max (replicated in 8-lane group)
    float denom = 0.f;     // running per-head sum of exp
    float4 acc = make_float4(0.f, 0.f, 0.f, 0.f);

    int sNext = (beg < end) ? __ldg(&g_csrc[beg]) : 0;
    for (int p = beg; p < end; p++) {
        int s = sNext;
        if (p + 1 < end) sNext = __ldg(&g_csrc[p + 1]);
        float4 a = __ldg((const float4*)(g_xl1 + (size_t)s * D1 + lane * 4));
        float e = lrelu(a.x + xr.x) * w.x + lrelu(a.y + xr.y) * w.y +
                  lrelu(a.z + xr.z) * w.z + lrelu(a.w + xr.w) * w.w;
        e += __shfl_xor_sync(full, e, 4);
        e += __shfl_xor_sync(full, e, 2);
        e += __shfl_xor_sync(full, e, 1);
        float mnew  = fmaxf(m, e);
        float scale = __expf(m - mnew);   // first iter: exp(-inf) = 0
        float wgt   = __expf(e - mnew);
        denom = denom * scale + wgt;
        acc.x = acc.x * scale + wgt * a.x;
        acc.y = acc.y * scale + wgt * a.y;
        acc.z = acc.z * scale + wgt * a.z;
        acc.w = acc.w * scale + wgt * a.w;
        m = mnew;
    }
    float inv = 1.f / (denom + 1e-16f);
    float4 bb = *(const float4*)(b1 + lane * 4);
    acc.x = acc.x * inv + bb.x; acc.y = acc.y * inv + bb.y;
    acc.z = acc.z * inv + bb.z; acc.w = acc.w * inv + bb.w;

    // LayerNorm over 128 features (warp-wide) + ELU
    float psum = acc.x + acc.y + acc.z + acc.w;
    float psq  = acc.x * acc.x + acc.y * acc.y + acc.z * acc.z + acc.w * acc.w;
    #pragma unroll
    for (int off = 16; off > 0; off >>= 1) {
        psum += __shfl_xor_sync(full, psum, off);
        psq  += __shfl_xor_sync(full, psq,  off);
    }
    float mean = psum * (1.f / 128.f);
    float var  = psq * (1.f / 128.f) - mean * mean;
    float rstd = rsqrtf(var + LN_EPS);
    float4 gg = *(const float4*)(g1  + lane * 4);
    float4 ee = *(const float4*)(be1 + lane * 4);
    float y0 = (acc.x - mean) * rstd * gg.x + ee.x;
    float y1 = (acc.y - mean) * rstd * gg.y + ee.y;
    float y2 = (acc.z - mean) * rstd * gg.z + ee.z;
    float y3 = (acc.w - mean) * rstd * gg.w + ee.w;
    y0 = y0 > 0.f ? y0 : expm1f(y0);
    y1 = y1 > 0.f ? y1 : expm1f(y1);
    y2 = y2 > 0.f ? y2 : expm1f(y2);
    y3 = y3 > 0.f ? y3 : expm1f(y3);
    *(float4*)(g_h1 + (size_t)node * D1 + lane * 4) = make_float4(y0, y1, y2, y3);
}

// ------- layer-2 fused: score + ONLINE softmax + aggregate -> output ---------
__global__ void agg2_kernel(const float* __restrict__ att2,
                            const float* __restrict__ b2,
                            float* __restrict__ out, int n) {
    const unsigned full = 0xffffffffu;
    int node = (blockIdx.x * blockDim.x + threadIdx.x) >> 5;
    int lane = threadIdx.x & 31;
    if (node >= n) return;
    int beg = __ldg(&g_rowptr[node]), end = __ldg(&g_rowptr[node + 1]);

    float xra = g_xr2[(size_t)node * OUTF + lane];
    float xrb = (lane < 8) ? g_xr2[(size_t)node * OUTF + 32 + lane] : 0.f;
    float wa = att2[lane];
    float wb = (lane < 8) ? att2[32 + lane] : 0.f;

    float m = -1e30f, denom = 0.f;
    float acc0 = 0.f, acc1 = 0.f;

    int sNext = (beg < end) ? __ldg(&g_csrc[beg]) : 0;
    for (int p = beg; p < end; p++) {
        int s = sNext;
        if (p + 1 < end) sNext = __ldg(&g_csrc[p + 1]);
        float va = __ldg(&g_xl2[(size_t)s * OUTF + lane]);
        float vb = (lane < 8) ? __ldg(&g_xl2[(size_t)s * OUTF + 32 + lane]) : 0.f;
        float e = lrelu(va + xra) * wa + ((lane < 8) ? lrelu(vb + xrb) * wb : 0.f);
        #pragma unroll
        for (int off = 16; off > 0; off >>= 1) e += __shfl_xor_sync(full, e, off);
        float mnew  = fmaxf(m, e);
        float scale = __expf(m - mnew);
        float wgt   = __expf(e - mnew);
        denom = denom * scale + wgt;
        acc0 = acc0 * scale + wgt * va;
        acc1 = acc1 * scale + wgt * vb;
        m = mnew;
    }
    float inv = 1.f / (denom + 1e-16f);
    out[(size_t)node * OUTF + lane] = acc0 * inv + b2[lane];
    if (lane < 8) out[(size_t)node * OUTF + 32 + lane] = acc1 * inv + b2[32 + lane];
}

// ---------------- launch -----------------------------------------------------
extern "C" void kernel_launch(void* const* d_in, const int* in_sizes, int n_in,
                              void* d_out, int out_size) {
    const float* x    = (const float*)d_in[0];
    const void*  eidx = d_in[1];
    const float* Wl1  = (const float*)d_in[2];
    const float* bl1  = (const float*)d_in[3];
    const float* Wr1  = (const float*)d_in[4];
    const float* br1  = (const float*)d_in[5];
    const float* att1 = (const float*)d_in[6];
    const float* b1   = (const float*)d_in[7];
    const float* g1   = (const float*)d_in[8];
    const float* be1  = (const float*)d_in[9];
    const float* Wl2  = (const float*)d_in[10];
    const float* bl2  = (const float*)d_in[11];
    const float* Wr2  = (const float*)d_in[12];
    const float* br2  = (const float*)d_in[13];
    const float* att2 = (const float*)d_in[14];
    const float* b2   = (const float*)d_in[15];
    float* out = (float*)d_out;

    int n = in_sizes[0] / 128;
    int E = in_sizes[1] / 2;
    int nb = (n + 255) / 256;

    // launches 1-3: CSR front half
    detect_kernel<<<1, 32>>>((const int*)eidx);
    zero_cnt_kernel<<<nb, 256>>>(n);
    convert_hist_kernel<<<(E + 255) / 256, 256>>>(eidx, E);

    // launch 4: gemm1 (independent of CSR) -> this is the launch ncu samples
    {
        dim3 grid((n + 127) / 128, 2);
        gemm1_kernel<<<grid, 256>>>(x, Wl1, bl1, Wr1, br1, n);
    }

    // CSR back half
    scan_a_kernel<<<nb, 256>>>(n);
    scan_b_kernel<<<1, 256>>>(nb);
    scan_c_kernel<<<nb, 256>>>(n, E);
    scatter_kernel<<<(E + 255) / 256, 256>>>(E);

    // layer 1 aggregate
    agg1_kernel<<<(n + 7) / 8, 256>>>(att1, b1, g1, be1, n);

    // layer 2
    {
        dim3 grid((n + 63) / 64, 2);
        gemm2_kernel<<<grid, 256>>>(Wl2, bl2, Wr2, br2, n);
    }
    agg2_kernel<<<(n + 7) / 8, 256>>>(att2, b2, out, n);
}